// round 14
// baseline (speedup 1.0000x reference)
#include <cuda_runtime.h>
#include <cuda_bf16.h>
#include <cstdint>

// DNN_84026740179139: embedding-bag mean + 3x[64x64 Linear+ReLU].
// R14: K2 re-tiled to 4 rows x 16 dims with DIM-PAIRED f32x2 packing:
//   - y2[r][dp] = (y[r][d0+2dp], y[r][d0+2dp+1]) -> W loads are native u64 from
//     shared (consecutive dims, ZERO W packs); only 4 x-dup packs per k.
//   - per warp-k: 5 LDS.128 (1 x conflict-free + 4 W broadcast) for 2048 MACs;
//     crossbar (~3.5us) now below the FFMA2 pipe floor (~7-8us).
//   - 128 thr, RPB=128, grid=128 (one wave); smem 50.2KB dynamic.
// K1 gather unchanged (R13).

#define BATCH   16384
#define DIMS    64
#define NNZ     50

typedef unsigned long long u64;

__device__ __forceinline__ u64 ffma2(u64 a, u64 b, u64 c) {
    u64 d; asm("fma.rn.f32x2 %0, %1, %2, %3;" : "=l"(d) : "l"(a), "l"(b), "l"(c)); return d;
}
__device__ __forceinline__ u64 add2(u64 a, u64 b) {
    u64 d; asm("add.rn.f32x2 %0, %1, %2;" : "=l"(d) : "l"(a), "l"(b)); return d;
}
__device__ __forceinline__ u64 mul2(u64 a, u64 b) {
    u64 d; asm("mul.rn.f32x2 %0, %1, %2;" : "=l"(d) : "l"(a), "l"(b)); return d;
}
__device__ __forceinline__ u64 pack2(float x, float y) {
    u64 d; asm("mov.b64 %0, {%1, %2};" : "=l"(d) : "f"(x), "f"(y)); return d;
}
__device__ __forceinline__ void unpack2(u64 d, float& x, float& y) {
    asm("mov.b64 {%0, %1}, %2;" : "=f"(x), "=f"(y) : "l"(d));
}

// 4MB scratch for pooled embeddings X[BATCH][DIMS]
__device__ float g_X[BATCH * DIMS];

// ================= K1 : gather + mean (unchanged from R13) =================
#define K1_RPB   16
#define K1_THR   256
#define K1_GRID  (BATCH / K1_RPB)   // 1024
#define IDXS     52                 // padded idx row stride (13 int4)

__global__ __launch_bounds__(K1_THR) void gather_kernel(
    const float* __restrict__ emb,
    const int*   __restrict__ fidx)
{
    __shared__ int sIdx[K1_RPB * IDXS];    // 3.3 KB, padded rows

    const int tid = threadIdx.x;
    {
        const int* src = fidx + blockIdx.x * K1_RPB * NNZ;
        #pragma unroll
        for (int s = 0; s < 4; s++) {
            const int i = tid + s * K1_THR;
            if (i < K1_RPB * NNZ) {
                const int r = i / NNZ;
                const int j = i - r * NNZ;
                sIdx[r * IDXS + j] = src[i];
            }
        }
    }
    __syncthreads();

    const int warp = tid >> 5;
    const int lane = tid & 31;
    const int half = lane >> 4;
    const int c    = lane & 15;
    const int lrow = 2 * warp + half;

    const ulonglong2* emb2 = (const ulonglong2*)emb;
    const int4* idx4 = (const int4*)(sIdx + lrow * IDXS);
    u64 a01 = 0ull, a23 = 0ull;

    #pragma unroll 3
    for (int g = 0; g < 12; g++) {
        const int4 id = idx4[g];
        const ulonglong2 v0 = __ldg(&emb2[(size_t)id.x * 16 + c]);
        const ulonglong2 v1 = __ldg(&emb2[(size_t)id.y * 16 + c]);
        const ulonglong2 v2 = __ldg(&emb2[(size_t)id.z * 16 + c]);
        const ulonglong2 v3 = __ldg(&emb2[(size_t)id.w * 16 + c]);
        a01 = add2(a01, v0.x); a23 = add2(a23, v0.y);
        a01 = add2(a01, v1.x); a23 = add2(a23, v1.y);
        a01 = add2(a01, v2.x); a23 = add2(a23, v2.y);
        a01 = add2(a01, v3.x); a23 = add2(a23, v3.y);
    }
    {
        const int4 id = idx4[12];
        const ulonglong2 v0 = __ldg(&emb2[(size_t)id.x * 16 + c]);
        const ulonglong2 v1 = __ldg(&emb2[(size_t)id.y * 16 + c]);
        a01 = add2(a01, v0.x); a23 = add2(a23, v0.y);
        a01 = add2(a01, v1.x); a23 = add2(a23, v1.y);
    }

    const u64 inv2 = pack2(1.0f / NNZ, 1.0f / NNZ);
    a01 = mul2(a01, inv2);
    a23 = mul2(a23, inv2);

    float f0, f1, f2, f3;
    unpack2(a01, f0, f1);
    unpack2(a23, f2, f3);
    const int grow = blockIdx.x * K1_RPB + lrow;
    *(float4*)(g_X + (size_t)grow * DIMS + 4 * c) = make_float4(f0, f1, f2, f3);
}

// ================= K2 : 3x (Linear + ReLU), dim-paired FFMA2 =================
#define K2_RPB   128
#define K2_THR   128
#define K2_GRID  (BATCH / K2_RPB)   // 128
#define XTS      132                // sXt row stride (mult of 4)
#define K2_SW_ELE   (DIMS * DIMS)          // 4096 floats
#define K2_SXT_ELE  (DIMS * XTS)           // 8448 floats
#define K2_SMEM_BYTES ((K2_SW_ELE + K2_SXT_ELE) * 4)   // 50176 B

__global__ __launch_bounds__(K2_THR) void mlp_kernel(
    const float* __restrict__ W0, const float* __restrict__ b0,
    const float* __restrict__ W1, const float* __restrict__ b1,
    const float* __restrict__ b2, const float* __restrict__ W2,
    float* __restrict__ out)
{
    extern __shared__ float smem[];
    float* sW  = smem;                 // [64][64] scalar weights
    float* sXt = smem + K2_SW_ELE;     // [64][XTS] x transposed: sXt[k*XTS + r]

    const int tid = threadIdx.x;

    // ---- stage W0 (1024 float4, 8/thread) ----
    {
        const float4* src = (const float4*)W0;
        float4*       dst = (float4*)sW;
        #pragma unroll
        for (int s = 0; s < 8; s++)
            dst[tid + s * K2_THR] = src[tid + s * K2_THR];
    }

    // ---- load X tile [128 rows x 64] (2048 float4, 16/thread) + transpose ----
    {
        const float4* X4 = (const float4*)(g_X + (size_t)blockIdx.x * K2_RPB * DIMS);
        #pragma unroll
        for (int s = 0; s < 16; s++) {
            const int idx = tid + s * K2_THR;       // 0..2047
            const int row = idx >> 4;               // 0..127
            const int cg  = idx & 15;               // dims 4cg..4cg+3
            const float4 v = X4[idx];
            sXt[(4 * cg + 0) * XTS + row] = v.x;
            sXt[(4 * cg + 1) * XTS + row] = v.y;
            sXt[(4 * cg + 2) * XTS + row] = v.z;
            sXt[(4 * cg + 3) * XTS + row] = v.w;
        }
    }
    __syncthreads();

    // ---- GEMM: thread tile = 4 rows x 16 dims (dim-paired u64 accum).
    //      r0 = 4*lane (128 rows across warp), d0 = 16*warp (uniform per warp) ----
    const int r0 = 4 * (tid & 31);
    const int d0 = 16 * (tid >> 5);

    const float* Wn[3] = {W0, W1, W2};
    const float* bn[3] = {b0, b1, b2};

    u64 y2[4][8];   // y2[r][dp] = (y[r0+r][d0+2dp], y[r0+r][d0+2dp+1])

    #pragma unroll
    for (int l = 0; l < 3; l++) {
        // bias: native u64 dim-pairs, same for all rows
        {
            const ulonglong2* b2p = (const ulonglong2*)(bn[l] + d0);
            const ulonglong2 ba = __ldg(b2p + 0);
            const ulonglong2 bb = __ldg(b2p + 1);
            const ulonglong2 bc = __ldg(b2p + 2);
            const ulonglong2 bd = __ldg(b2p + 3);
            #pragma unroll
            for (int r = 0; r < 4; r++) {
                y2[r][0] = ba.x; y2[r][1] = ba.y;
                y2[r][2] = bb.x; y2[r][3] = bb.y;
                y2[r][4] = bc.x; y2[r][5] = bc.y;
                y2[r][6] = bd.x; y2[r][7] = bd.y;
            }
        }

        #pragma unroll 4
        for (int k = 0; k < DIMS; k++) {
            // x rows r0..r0+3: 1 LDS.128, conflict-free (lane-permutation of banks)
            const float4 xv = *(const float4*)(sXt + k * XTS + r0);
            // W dims d0..d0+15 as native u64 pairs: 4 LDS.128, warp-uniform
            const float* wk = sW + k * DIMS + d0;
            const ulonglong2 wA = *(const ulonglong2*)(wk);
            const ulonglong2 wB = *(const ulonglong2*)(wk + 4);
            const ulonglong2 wC = *(const ulonglong2*)(wk + 8);
            const ulonglong2 wD = *(const ulonglong2*)(wk + 12);
            const u64 w2[8] = {wA.x, wA.y, wB.x, wB.y, wC.x, wC.y, wD.x, wD.y};
            // duplicate x scalars (4 packs, ALU)
            const u64 xr[4] = {pack2(xv.x, xv.x), pack2(xv.y, xv.y),
                               pack2(xv.z, xv.z), pack2(xv.w, xv.w)};
            #pragma unroll
            for (int r = 0; r < 4; r++)
                #pragma unroll
                for (int dp = 0; dp < 8; dp++)
                    y2[r][dp] = ffma2(xr[r], w2[dp], y2[r][dp]);
        }

        // ReLU
        #pragma unroll
        for (int r = 0; r < 4; r++)
            #pragma unroll
            for (int dp = 0; dp < 8; dp++) {
                float a, b;
                unpack2(y2[r][dp], a, b);
                y2[r][dp] = pack2(fmaxf(a, 0.f), fmaxf(b, 0.f));
            }

        if (l < 2) {
            __syncthreads();
            // stage next layer's W
            {
                const float4* src = (const float4*)Wn[l + 1];
                float4*       dst = (float4*)sW;
                #pragma unroll
                for (int s = 0; s < 8; s++)
                    dst[tid + s * K2_THR] = src[tid + s * K2_THR];
            }
            // writeback transposed: sXt[(d0+2dp+e)*XTS + r0+r] (scalar STS)
            #pragma unroll
            for (int r = 0; r < 4; r++)
                #pragma unroll
                for (int dp = 0; dp < 8; dp++) {
                    float a, b;
                    unpack2(y2[r][dp], a, b);
                    sXt[(d0 + 2 * dp)     * XTS + r0 + r] = a;
                    sXt[(d0 + 2 * dp + 1) * XTS + r0 + r] = b;
                }
            __syncthreads();
        }
    }

    // ---- store out[B,64]: 4 rows x 16 dims = 16 STG.128 ----
    #pragma unroll
    for (int r = 0; r < 4; r++) {
        float f[16];
        #pragma unroll
        for (int dp = 0; dp < 8; dp++)
            unpack2(y2[r][dp], f[2 * dp], f[2 * dp + 1]);
        float* o = out + (size_t)(blockIdx.x * K2_RPB + r0 + r) * DIMS + d0;
        *(float4*)(o)      = make_float4(f[0],  f[1],  f[2],  f[3]);
        *(float4*)(o + 4)  = make_float4(f[4],  f[5],  f[6],  f[7]);
        *(float4*)(o + 8)  = make_float4(f[8],  f[9],  f[10], f[11]);
        *(float4*)(o + 12) = make_float4(f[12], f[13], f[14], f[15]);
    }
}

extern "C" void kernel_launch(void* const* d_in, const int* in_sizes, int n_in,
                              void* d_out, int out_size)
{
    // Resolve inputs by element count:
    //   emb_table 6400000 f32; feature_indices 819200 i32 (first occurrence);
    //   W* 4096 f32 in order; b* 64 f32 in order.
    const float* emb  = nullptr;
    const int*   fidx = nullptr;
    const float* W[3] = {nullptr, nullptr, nullptr};
    const float* b[3] = {nullptr, nullptr, nullptr};
    int wi = 0, bi = 0;

    for (int i = 0; i < n_in; i++) {
        const int sz = in_sizes[i];
        if (sz == 100000 * 64) {
            emb = (const float*)d_in[i];
        } else if (sz == BATCH * NNZ) {
            if (!fidx) fidx = (const int*)d_in[i];
        } else if (sz == DIMS * DIMS) {
            if (wi < 3) W[wi++] = (const float*)d_in[i];
        } else if (sz == DIMS) {
            if (bi < 3) b[bi++] = (const float*)d_in[i];
        }
    }

    float* out = (float*)d_out;

    // 50.2KB dynamic smem needs opt-in (host-side attribute; capture-safe)
    cudaFuncSetAttribute(mlp_kernel,
                         cudaFuncAttributeMaxDynamicSharedMemorySize,
                         K2_SMEM_BYTES);

    gather_kernel<<<K1_GRID, K1_THR>>>(emb, fidx);
    mlp_kernel<<<K2_GRID, K2_THR, K2_SMEM_BYTES>>>(
        W[0], b[0], W[1], b[1], b[2], W[2], out);
}

// round 15
// speedup vs baseline: 1.0449x; 1.0449x over previous
#include <cuda_runtime.h>
#include <cuda_bf16.h>
#include <cstdint>

// DNN_84026740179139: embedding-bag mean + 3x[64x64 Linear+ReLU].
// R15: K2 = dim-paired FFMA2 inner loop (R14-validated: L1 50%->32%) at a sane
//   launch shape: RPB=64, 256 thr, grid=256 -> 2048 warps (13.8/SM), tile
//   2 rows x 8 dims (16 outputs, ~60 regs). Per thread-k: 1 LDS.64 (x pair) +
//   2 LDS.128 (W native u64 pairs, broadcast) + 2 packs + 8 FFMA2.
//   Crossbar floor ~7us == FFMA2 floor ~7us.
// K1 gather unchanged (R13).

#define BATCH   16384
#define DIMS    64
#define NNZ     50

typedef unsigned long long u64;

__device__ __forceinline__ u64 ffma2(u64 a, u64 b, u64 c) {
    u64 d; asm("fma.rn.f32x2 %0, %1, %2, %3;" : "=l"(d) : "l"(a), "l"(b), "l"(c)); return d;
}
__device__ __forceinline__ u64 add2(u64 a, u64 b) {
    u64 d; asm("add.rn.f32x2 %0, %1, %2;" : "=l"(d) : "l"(a), "l"(b)); return d;
}
__device__ __forceinline__ u64 mul2(u64 a, u64 b) {
    u64 d; asm("mul.rn.f32x2 %0, %1, %2;" : "=l"(d) : "l"(a), "l"(b)); return d;
}
__device__ __forceinline__ u64 pack2(float x, float y) {
    u64 d; asm("mov.b64 %0, {%1, %2};" : "=l"(d) : "f"(x), "f"(y)); return d;
}
__device__ __forceinline__ void unpack2(u64 d, float& x, float& y) {
    asm("mov.b64 {%0, %1}, %2;" : "=f"(x), "=f"(y) : "l"(d));
}

// 4MB scratch for pooled embeddings X[BATCH][DIMS]
__device__ float g_X[BATCH * DIMS];

// ================= K1 : gather + mean (unchanged from R13) =================
#define K1_RPB   16
#define K1_THR   256
#define K1_GRID  (BATCH / K1_RPB)   // 1024
#define IDXS     52                 // padded idx row stride (13 int4)

__global__ __launch_bounds__(K1_THR) void gather_kernel(
    const float* __restrict__ emb,
    const int*   __restrict__ fidx)
{
    __shared__ int sIdx[K1_RPB * IDXS];    // 3.3 KB, padded rows

    const int tid = threadIdx.x;
    {
        const int* src = fidx + blockIdx.x * K1_RPB * NNZ;
        #pragma unroll
        for (int s = 0; s < 4; s++) {
            const int i = tid + s * K1_THR;
            if (i < K1_RPB * NNZ) {
                const int r = i / NNZ;
                const int j = i - r * NNZ;
                sIdx[r * IDXS + j] = src[i];
            }
        }
    }
    __syncthreads();

    const int warp = tid >> 5;
    const int lane = tid & 31;
    const int half = lane >> 4;
    const int c    = lane & 15;
    const int lrow = 2 * warp + half;

    const ulonglong2* emb2 = (const ulonglong2*)emb;
    const int4* idx4 = (const int4*)(sIdx + lrow * IDXS);
    u64 a01 = 0ull, a23 = 0ull;

    #pragma unroll 3
    for (int g = 0; g < 12; g++) {
        const int4 id = idx4[g];
        const ulonglong2 v0 = __ldg(&emb2[(size_t)id.x * 16 + c]);
        const ulonglong2 v1 = __ldg(&emb2[(size_t)id.y * 16 + c]);
        const ulonglong2 v2 = __ldg(&emb2[(size_t)id.z * 16 + c]);
        const ulonglong2 v3 = __ldg(&emb2[(size_t)id.w * 16 + c]);
        a01 = add2(a01, v0.x); a23 = add2(a23, v0.y);
        a01 = add2(a01, v1.x); a23 = add2(a23, v1.y);
        a01 = add2(a01, v2.x); a23 = add2(a23, v2.y);
        a01 = add2(a01, v3.x); a23 = add2(a23, v3.y);
    }
    {
        const int4 id = idx4[12];
        const ulonglong2 v0 = __ldg(&emb2[(size_t)id.x * 16 + c]);
        const ulonglong2 v1 = __ldg(&emb2[(size_t)id.y * 16 + c]);
        a01 = add2(a01, v0.x); a23 = add2(a23, v0.y);
        a01 = add2(a01, v1.x); a23 = add2(a23, v1.y);
    }

    const u64 inv2 = pack2(1.0f / NNZ, 1.0f / NNZ);
    a01 = mul2(a01, inv2);
    a23 = mul2(a23, inv2);

    float f0, f1, f2, f3;
    unpack2(a01, f0, f1);
    unpack2(a23, f2, f3);
    const int grow = blockIdx.x * K1_RPB + lrow;
    *(float4*)(g_X + (size_t)grow * DIMS + 4 * c) = make_float4(f0, f1, f2, f3);
}

// ================= K2 : 3x (Linear + ReLU), dim-paired FFMA2 =================
#define K2_RPB   64
#define K2_THR   256
#define K2_GRID  (BATCH / K2_RPB)   // 256
#define XTS      68                 // sXt row stride (mult of 4)

__global__ __launch_bounds__(K2_THR) void mlp_kernel(
    const float* __restrict__ W0, const float* __restrict__ b0,
    const float* __restrict__ W1, const float* __restrict__ b1,
    const float* __restrict__ b2, const float* __restrict__ W2,
    float* __restrict__ out)
{
    __shared__ float sW[DIMS * DIMS];      // 16 KB scalar weights
    __shared__ float sXt[DIMS * XTS];      // 17.4 KB x transposed: sXt[k*XTS + r]

    const int tid = threadIdx.x;

    // ---- stage W0 (1024 float4, 4/thread) ----
    {
        const float4* src = (const float4*)W0;
        float4*       dst = (float4*)sW;
        #pragma unroll
        for (int s = 0; s < 4; s++)
            dst[tid + s * K2_THR] = src[tid + s * K2_THR];
    }

    // ---- load X tile [64 rows x 64] (1024 float4, 4/thread) + transpose ----
    {
        const float4* X4 = (const float4*)(g_X + (size_t)blockIdx.x * K2_RPB * DIMS);
        #pragma unroll
        for (int s = 0; s < 4; s++) {
            const int idx = tid + s * K2_THR;       // 0..1023
            const int row = idx >> 4;               // 0..63
            const int cg  = idx & 15;               // dims 4cg..4cg+3
            const float4 v = X4[idx];
            sXt[(4 * cg + 0) * XTS + row] = v.x;
            sXt[(4 * cg + 1) * XTS + row] = v.y;
            sXt[(4 * cg + 2) * XTS + row] = v.z;
            sXt[(4 * cg + 3) * XTS + row] = v.w;
        }
    }
    __syncthreads();

    // ---- GEMM: thread tile = 2 rows x 8 dims (dim-paired u64 accum).
    //      r0 = 2*(tid&31) rows, d0 = 8*(tid>>5) dims (warp-uniform) ----
    const int r0 = 2 * (tid & 31);
    const int d0 = 8 * (tid >> 5);

    const float* Wn[3] = {W0, W1, W2};
    const float* bn[3] = {b0, b1, b2};

    u64 y2[2][4];   // y2[r][dp] = (y[r0+r][d0+2dp], y[r0+r][d0+2dp+1])

    #pragma unroll
    for (int l = 0; l < 3; l++) {
        // bias: native u64 dim-pairs
        {
            const ulonglong2* b2p = (const ulonglong2*)(bn[l] + d0);
            const ulonglong2 ba = __ldg(b2p + 0);
            const ulonglong2 bb = __ldg(b2p + 1);
            y2[0][0] = ba.x; y2[0][1] = ba.y; y2[0][2] = bb.x; y2[0][3] = bb.y;
            y2[1][0] = ba.x; y2[1][1] = ba.y; y2[1][2] = bb.x; y2[1][3] = bb.y;
        }

        #pragma unroll 8
        for (int k = 0; k < DIMS; k++) {
            // x rows r0, r0+1: LDS.64 (8B aligned; 32 lanes cover 256B contiguous)
            const float2 xv = *(const float2*)(sXt + k * XTS + r0);
            // W dims d0..d0+7 as native u64 pairs: 2 LDS.128, warp-uniform
            const float* wk = sW + k * DIMS + d0;
            const ulonglong2 wA = *(const ulonglong2*)(wk);
            const ulonglong2 wB = *(const ulonglong2*)(wk + 4);
            // duplicate x scalars (2 packs, ALU)
            const u64 xa = pack2(xv.x, xv.x);
            const u64 xb = pack2(xv.y, xv.y);
            y2[0][0] = ffma2(xa, wA.x, y2[0][0]);
            y2[0][1] = ffma2(xa, wA.y, y2[0][1]);
            y2[0][2] = ffma2(xa, wB.x, y2[0][2]);
            y2[0][3] = ffma2(xa, wB.y, y2[0][3]);
            y2[1][0] = ffma2(xb, wA.x, y2[1][0]);
            y2[1][1] = ffma2(xb, wA.y, y2[1][1]);
            y2[1][2] = ffma2(xb, wB.x, y2[1][2]);
            y2[1][3] = ffma2(xb, wB.y, y2[1][3]);
        }

        // ReLU
        #pragma unroll
        for (int r = 0; r < 2; r++)
            #pragma unroll
            for (int dp = 0; dp < 4; dp++) {
                float a, b;
                unpack2(y2[r][dp], a, b);
                y2[r][dp] = pack2(fmaxf(a, 0.f), fmaxf(b, 0.f));
            }

        if (l < 2) {
            __syncthreads();
            // stage next layer's W
            {
                const float4* src = (const float4*)Wn[l + 1];
                float4*       dst = (float4*)sW;
                #pragma unroll
                for (int s = 0; s < 4; s++)
                    dst[tid + s * K2_THR] = src[tid + s * K2_THR];
            }
            // writeback transposed: scalar STS (16/thread)
            #pragma unroll
            for (int r = 0; r < 2; r++)
                #pragma unroll
                for (int dp = 0; dp < 4; dp++) {
                    float a, b;
                    unpack2(y2[r][dp], a, b);
                    sXt[(d0 + 2 * dp)     * XTS + r0 + r] = a;
                    sXt[(d0 + 2 * dp + 1) * XTS + r0 + r] = b;
                }
            __syncthreads();
        }
    }

    // ---- store out[B,64]: 2 rows x 8 dims = 4 STG.128 ----
    #pragma unroll
    for (int r = 0; r < 2; r++) {
        float f[8];
        #pragma unroll
        for (int dp = 0; dp < 4; dp++)
            unpack2(y2[r][dp], f[2 * dp], f[2 * dp + 1]);
        float* o = out + (size_t)(blockIdx.x * K2_RPB + r0 + r) * DIMS + d0;
        *(float4*)(o)     = make_float4(f[0], f[1], f[2], f[3]);
        *(float4*)(o + 4) = make_float4(f[4], f[5], f[6], f[7]);
    }
}

extern "C" void kernel_launch(void* const* d_in, const int* in_sizes, int n_in,
                              void* d_out, int out_size)
{
    // Resolve inputs by element count:
    //   emb_table 6400000 f32; feature_indices 819200 i32 (first occurrence);
    //   W* 4096 f32 in order; b* 64 f32 in order.
    const float* emb  = nullptr;
    const int*   fidx = nullptr;
    const float* W[3] = {nullptr, nullptr, nullptr};
    const float* b[3] = {nullptr, nullptr, nullptr};
    int wi = 0, bi = 0;

    for (int i = 0; i < n_in; i++) {
        const int sz = in_sizes[i];
        if (sz == 100000 * 64) {
            emb = (const float*)d_in[i];
        } else if (sz == BATCH * NNZ) {
            if (!fidx) fidx = (const int*)d_in[i];
        } else if (sz == DIMS * DIMS) {
            if (wi < 3) W[wi++] = (const float*)d_in[i];
        } else if (sz == DIMS) {
            if (bi < 3) b[bi++] = (const float*)d_in[i];
        }
    }

    float* out = (float*)d_out;
    gather_kernel<<<K1_GRID, K1_THR>>>(emb, fidx);
    mlp_kernel<<<K2_GRID, K2_THR>>>(W[0], b[0], W[1], b[1], b[2], W[2], out);
}